// round 14
// baseline (speedup 1.0000x reference)
#include <cuda_runtime.h>
#include <cuda_bf16.h>
#include <cstdint>

// Problem constants
#define TSEQ 1024
#define BATCH 64
#define HID 128
#define G4 512            // 4*HID
#define XGHALF (TSEQ*BATCH*G4)   // per-direction xg elements

// ---------------- scratch (static device globals; no allocations) -------------
__device__ float g_xg[2 * TSEQ * BATCH * G4];     // [dir][T][B][512]
__device__ uint16_t g_ahi[TSEQ * BATCH * 256];    // A hi (bf16), layer 1 or 2
__device__ uint16_t g_alo[TSEQ * BATCH * 256];    // A lo (bf16)
__device__ uint16_t g_whi[512 * 768];             // W hi: fw1|bw1|fw2|bw2
__device__ uint16_t g_wlo[512 * 768];             // W lo

// W offsets (bf16 elements) — fw1:128 cols, bw1:128, fw2:256, bw2:256
#define WOFF_FW1 0
#define WOFF_BW1 (512 * 128)
#define WOFF_FW2 (512 * 256)
#define WOFF_BW2 (512 * 512)

// ---------------- MUFU activations (short chains; limits exact at +/-inf) -----
__device__ __forceinline__ float fsig_mufu(float x) {
    float e;
    asm("ex2.approx.f32 %0, %1;" : "=f"(e) : "f"(-1.4426950408889634f * x));
    float r;
    asm("rcp.approx.f32 %0, %1;" : "=f"(r) : "f"(1.0f + e));
    return r;
}
__device__ __forceinline__ float ftanh_mufu(float x) {
    float e;
    asm("ex2.approx.f32 %0, %1;" : "=f"(e) : "f"(-2.8853900817779268f * x));
    float r;
    asm("rcp.approx.f32 %0, %1;" : "=f"(r) : "f"(1.0f + e));
    return fmaf(2.0f, r, -1.0f);
}

// ---------------- bf16 pack/unpack --------------------------------------------
__device__ __forceinline__ uint32_t pack_bf2(float lo, float hi) {
    uint32_t r;   // PTX: cvt.rn.bf16x2.f32 d, a(high), b(low)
    asm("cvt.rn.bf16x2.f32 %0, %1, %2;" : "=r"(r) : "f"(hi), "f"(lo));
    return r;
}
__device__ __forceinline__ float bflo(uint32_t b) {
    return __int_as_float((int)(b << 16));
}
__device__ __forceinline__ float bfhi(uint32_t b) {
    return __int_as_float((int)(b & 0xFFFF0000u));
}
__device__ __forceinline__ void split4(float4 v, uint2& hi, uint2& lo) {
    uint32_t h0 = pack_bf2(v.x, v.y), h1 = pack_bf2(v.z, v.w);
    uint32_t l0 = pack_bf2(v.x - bflo(h0), v.y - bfhi(h0));
    uint32_t l1 = pack_bf2(v.z - bflo(h1), v.w - bfhi(h1));
    hi = make_uint2(h0, h1);
    lo = make_uint2(l0, l1);
}

// ---------------- warp-MMA primitives (baseline PTX, sm_80+) -------------------
__device__ __forceinline__ uint32_t smem_u32(const void* p) {
    uint32_t a;
    asm("{ .reg .u64 t; cvta.to.shared.u64 t, %1; cvt.u32.u64 %0, t; }"
        : "=r"(a) : "l"(p));
    return a;
}
__device__ __forceinline__ void ldmx4(uint32_t* r, uint32_t addr) {
    asm volatile("ldmatrix.sync.aligned.m8n8.x4.shared.b16 {%0,%1,%2,%3}, [%4];"
                 : "=r"(r[0]), "=r"(r[1]), "=r"(r[2]), "=r"(r[3]) : "r"(addr));
}
__device__ __forceinline__ void mma16816(float* c, const uint32_t* a,
                                         const uint32_t* b) {
    asm volatile(
        "mma.sync.aligned.m16n8k16.row.col.f32.bf16.bf16.f32 "
        "{%0,%1,%2,%3}, {%4,%5,%6,%7}, {%8,%9}, {%0,%1,%2,%3};"
        : "+f"(c[0]), "+f"(c[1]), "+f"(c[2]), "+f"(c[3])
        : "r"(a[0]), "r"(a[1]), "r"(a[2]), "r"(a[3]), "r"(b[0]), "r"(b[1]));
}
__device__ __forceinline__ void cp16(uint32_t dst, const void* src) {
    asm volatile("cp.async.ca.shared.global [%0], [%1], 16;"
                 :: "r"(dst), "l"(src));
}
#define CP_COMMIT() asm volatile("cp.async.commit_group;" ::: "memory")
#define CP_WAIT0()  asm volatile("cp.async.wait_group 0;" ::: "memory")
// SW128-style swizzle for 128B-row tiles (row stride 128B = 64 bf16)
__device__ __forceinline__ uint32_t swz(uint32_t off) {
    return off ^ ((off >> 3) & 0x70);
}

// ---------------- converters ---------------------------------------------------
// x [B,T,128] -> (transpose to [T,B,128]) hi/lo bf16
__global__ void conv_x(const float4* __restrict__ x,
                       uint2* __restrict__ hi, uint2* __restrict__ lo) {
    int i = blockIdx.x * blockDim.x + threadIdx.x;   // over T*B*32 float4s
    if (i >= TSEQ * BATCH * 32) return;
    int t  = i >> 11;
    int r  = i & 2047;
    int b  = r >> 5;
    int k4 = r & 31;
    float4 v = x[((size_t)b * TSEQ + t) * 32 + k4];
    split4(v, hi[i], lo[i]);
}
// generic fp32 -> bf16 hi/lo split (n4 float4s)
__global__ void conv_split(const float4* __restrict__ src,
                           uint2* __restrict__ hi, uint2* __restrict__ lo,
                           int n4) {
    int i = blockIdx.x * blockDim.x + threadIdx.x;
    if (i >= n4) return;
    split4(src[i], hi[i], lo[i]);
}

// ---------------- tensor-core GEMM (bf16 pre-split, cp.async pipeline) ---------
// C[M,512] = A[M,K]*W[512,K]^T + bias1 + bias2.  Per CTA: 128x128 C-tile,
// 8 warps in 2(m)x4(n), each 64x32 via m16n8k16. K staged 64/iter, double-buffered.
#define KSTAGE 64
#define TILE_BY (128 * KSTAGE * 2)     // 16384 B per bf16 tile
#define STAGE_BY (4 * TILE_BY)         // AH, AL, BH, BL = 64 KB
#define GEMM_SMEM (2 * STAGE_BY)       // double buffer = 128 KB

__global__ __launch_bounds__(256, 1) void gemm_tc(
    const uint16_t* __restrict__ Ahi, const uint16_t* __restrict__ Alo,
    const uint16_t* __restrict__ Whi, const uint16_t* __restrict__ Wlo,
    const float* __restrict__ bias1, const float* __restrict__ bias2,
    float* __restrict__ C, int K)
{
    extern __shared__ __align__(1024) char smem[];
    uint32_t sb = smem_u32(smem);

    int tid = threadIdx.x;
    int wid = tid >> 5;
    int l   = tid & 31;
    int wm  = wid >> 2;          // 0..1  (64-row slab)
    int wn  = wid & 3;           // 0..3  (32-col slab)
    int bm  = blockIdx.x * 128;
    int bn  = blockIdx.y * 128;

    float acc[4][4][4];
#pragma unroll
    for (int i = 0; i < 4; i++)
#pragma unroll
        for (int jj = 0; jj < 4; jj++)
#pragma unroll
            for (int e = 0; e < 4; e++) acc[i][jj][e] = 0.f;

    // loader: thread -> row tid>>1, four 16B chunks at col-chunks (tid&1)*4+q
    int lrow = tid >> 1;
    const uint16_t* Arow_h = Ahi + (size_t)(bm + lrow) * K;
    const uint16_t* Arow_l = Alo + (size_t)(bm + lrow) * K;
    const uint16_t* Wrow_h = Whi + (size_t)(bn + lrow) * K;
    const uint16_t* Wrow_l = Wlo + (size_t)(bn + lrow) * K;

    // ldmatrix lane address components (within a 128x64 tile)
    int a_row = (l & 7) + ((l >> 3) & 1) * 8;
    int a_cb  = ((l >> 4) & 1) * 8;
    int b_row = (l & 7) + ((l >> 4) & 1) * 8;
    int b_cb  = ((l >> 3) & 1) * 8;

    int nst = K / KSTAGE;

    // --- stage loader (cp.async, 16 chunks per thread) ---
#define LOAD_STAGE(st, buf)                                                   \
    do {                                                                      \
        uint32_t base_ = sb + (buf) * STAGE_BY;                               \
        int k0_ = (st) * KSTAGE;                                              \
        _Pragma("unroll")                                                     \
        for (int q_ = 0; q_ < 4; q_++) {                                      \
            int c8_ = (tid & 1) * 4 + q_;                                     \
            uint32_t d_ = swz((uint32_t)(lrow * 128 + c8_ * 16));             \
            int so_ = k0_ + c8_ * 8;                                          \
            cp16(base_ + 0 * TILE_BY + d_, Arow_h + so_);                     \
            cp16(base_ + 1 * TILE_BY + d_, Arow_l + so_);                     \
            cp16(base_ + 2 * TILE_BY + d_, Wrow_h + so_);                     \
            cp16(base_ + 3 * TILE_BY + d_, Wrow_l + so_);                     \
        }                                                                     \
        CP_COMMIT();                                                          \
    } while (0)

    LOAD_STAGE(0, 0);

    for (int st = 0; st < nst; st++) {
        int buf = st & 1;
        CP_WAIT0();
        __syncthreads();
        if (st + 1 < nst) LOAD_STAGE(st + 1, buf ^ 1);

        uint32_t sAH = sb + buf * STAGE_BY;
        uint32_t sAL = sAH + TILE_BY;
        uint32_t sBH = sAH + 2 * TILE_BY;
        uint32_t sBL = sAH + 3 * TILE_BY;

#pragma unroll
        for (int kk = 0; kk < KSTAGE / 16; kk++) {
            int C0 = kk * 16;
            uint32_t bh[8], bl[8];
#pragma unroll
            for (int half = 0; half < 2; half++) {
                uint32_t off = swz((uint32_t)(
                    (wn * 32 + half * 16 + b_row) * 128 + (C0 + b_cb) * 2));
                ldmx4(bh + half * 4, sBH + off);
                ldmx4(bl + half * 4, sBL + off);
            }
#pragma unroll
            for (int mt = 0; mt < 4; mt++) {
                uint32_t off = swz((uint32_t)(
                    (wm * 64 + mt * 16 + a_row) * 128 + (C0 + a_cb) * 2));
                uint32_t ah[4], al[4];
                ldmx4(ah, sAH + off);
                ldmx4(al, sAL + off);
#pragma unroll
                for (int nt = 0; nt < 4; nt++) {
                    mma16816(acc[mt][nt], ah, bh + nt * 2);
                    mma16816(acc[mt][nt], al, bh + nt * 2);
                    mma16816(acc[mt][nt], ah, bl + nt * 2);
                }
            }
        }
        __syncthreads();
    }

    // epilogue: bias + store
    int crow = l >> 2;
    int ccol = (l & 3) * 2;
#pragma unroll
    for (int nt = 0; nt < 4; nt++) {
        int gc = bn + wn * 32 + nt * 8 + ccol;
        float b0 = __ldg(&bias1[gc])     + __ldg(&bias2[gc]);
        float b1 = __ldg(&bias1[gc + 1]) + __ldg(&bias2[gc + 1]);
#pragma unroll
        for (int mt = 0; mt < 4; mt++) {
            int gr = bm + wm * 64 + mt * 16 + crow;
            float* p0 = C + (size_t)gr * G4 + gc;
            p0[0] = acc[mt][nt][0] + b0;
            p0[1] = acc[mt][nt][1] + b1;
            float* p1 = C + (size_t)(gr + 8) * G4 + gc;
            p1[0] = acc[mt][nt][2] + b0;
            p1[1] = acc[mt][nt][3] + b1;
        }
    }
}

// ---------------- recurrent LSTM scan: 256 thr, shuffle gate exchange ----------
// Warp w handles units [16w, 16w+16). Lane 2k   owns (i,g) of unit u=16w+k,
//                                     lane 2k+1 owns (f,o) of the same unit.
// Rows: even lane -> u, u+256 ; odd lane -> u+128, u+384.
// Gate exchange via __shfl_xor(.,1) — no smem, no extra barrier.
// h ping-pong double buffer -> ONE __syncthreads per step.
#define RK2 88
#define SKQ2 ((128 - RK2) / 4)          // 10 smem quads per row
#define REC2_SMEM (SKQ2 * G4 * 16 + 2 * HID * 4)

__global__ __launch_bounds__(256, 1) void lstm_rec2(
    const float* __restrict__ xg,        // [dir][T][B][512]
    const float* __restrict__ Whh0,      // fw weights [512][128]
    const float* __restrict__ Whh1,      // bw weights [512][128]
    float* __restrict__ out,             // fp32 h output (layer 2) or unused
    int outT, int outB,                  // strides (floats) for t and b
    uint16_t* __restrict__ shi,          // if non-null: write bf16 hi/lo split
    uint16_t* __restrict__ slo)          //   at [t][b][dir*128+u] (layer 1)
{
    extern __shared__ float sm[];
    float4* ws4 = (float4*)sm;                   // SKQ2*512 quads: [q][row]
    float* hbuf = sm + SKQ2 * 4 * G4;            // 2 x 128 ping-pong (16B align)

    int tid = threadIdx.x;
    int b   = blockIdx.x;
    int dir = blockIdx.y;
    const float* Whh = dir ? Whh1 : Whh0;

    int u   = (tid >> 5) * 16 + ((tid & 31) >> 1);   // hidden unit
    int odd = tid & 1;
    int r0 = u + odd * 128;              // i (even) / f (odd)
    int r1 = u + 256 + odd * 128;        // g (even) / o (odd)

    const float4* W0 = (const float4*)(Whh + (size_t)r0 * 128);
    const float4* W1 = (const float4*)(Whh + (size_t)r1 * 128);
    float w0[RK2], w1[RK2];
#pragma unroll
    for (int q = 0; q < RK2 / 4; q++) {
        float4 v = W0[q];
        w0[4 * q + 0] = v.x; w0[4 * q + 1] = v.y;
        w0[4 * q + 2] = v.z; w0[4 * q + 3] = v.w;
        v = W1[q];
        w1[4 * q + 0] = v.x; w1[4 * q + 1] = v.y;
        w1[4 * q + 2] = v.z; w1[4 * q + 3] = v.w;
    }
#pragma unroll
    for (int q = RK2 / 4; q < 32; q++) {
        ws4[(q - RK2 / 4) * G4 + r0] = W0[q];
        ws4[(q - RK2 / 4) * G4 + r1] = W1[q];
    }

    if (tid < 2 * HID) hbuf[tid] = 0.f;
    float c = 0.f;
    __syncthreads();

    size_t xgb0 = (size_t)dir * XGHALF + (size_t)b * G4 + r0;
    size_t xgb1 = (size_t)dir * XGHALF + (size_t)b * G4 + r1;
    int t0 = dir ? (TSEQ - 1) : 0;
    float xg0 = __ldg(xg + xgb0 + (size_t)t0 * (BATCH * G4));
    float xg1 = __ldg(xg + xgb1 + (size_t)t0 * (BATCH * G4));

    for (int s = 0; s < TSEQ; s++) {
        int t = dir ? (TSEQ - 1 - s) : s;
        int tn = dir ? max(t - 1, 0) : min(t + 1, TSEQ - 1);
        float xg0n = __ldg(xg + xgb0 + (size_t)tn * (BATCH * G4));
        float xg1n = __ldg(xg + xgb1 + (size_t)tn * (BATCH * G4));

        const float4* hs4 = (const float4*)(hbuf + (s & 1) * HID);
        float a0 = xg0, a1 = 0.f, a2 = 0.f, a3 = 0.f;
        float b0 = xg1, b1 = 0.f, b2 = 0.f, b3 = 0.f;
#pragma unroll
        for (int q = 0; q < RK2 / 4; q++) {      // register half, both rows
            float4 hv = hs4[q];
            a0 += w0[4 * q + 0] * hv.x;
            a1 += w0[4 * q + 1] * hv.y;
            a2 += w0[4 * q + 2] * hv.z;
            a3 += w0[4 * q + 3] * hv.w;
            b0 += w1[4 * q + 0] * hv.x;
            b1 += w1[4 * q + 1] * hv.y;
            b2 += w1[4 * q + 2] * hv.z;
            b3 += w1[4 * q + 3] * hv.w;
        }
#pragma unroll
        for (int q = 0; q < SKQ2; q++) {         // smem half, both rows
            float4 hv = hs4[RK2 / 4 + q];
            float4 uq = ws4[q * G4 + r0];
            float4 vq = ws4[q * G4 + r1];
            a0 += uq.x * hv.x; a1 += uq.y * hv.y;
            a2 += uq.z * hv.z; a3 += uq.w * hv.w;
            b0 += vq.x * hv.x; b1 += vq.y * hv.y;
            b2 += vq.z * hv.z; b3 += vq.w * hv.w;
        }
        float pre0 = (a0 + a1) + (a2 + a3);      // i (even) / f (odd)
        float pre1 = (b0 + b1) + (b2 + b3);      // g (even) / o (odd)

        float v0 = fsig_mufu(pre0);                     // i or f
        float v1 = odd ? fsig_mufu(pre1) : ftanh_mufu(pre1);  // o or g

        // partner exchange within the lane pair
        float pv0 = __shfl_xor_sync(0xFFFFFFFFu, v0, 1);   // f (for even)
        float pv1 = __shfl_xor_sync(0xFFFFFFFFu, v1, 1);   // o (for even)

        if (!odd) {
            float iv = v0, gv = v1, fv = pv0, ov = pv1;
            c = fmaf(fv, c, iv * gv);
            float h = ov * ftanh_mufu(c);
            hbuf[((s & 1) ^ 1) * HID + u] = h;
            if (shi) {
                size_t idx = (size_t)t * (BATCH * 256) + b * 256 + dir * 128 + u;
                uint32_t ph = pack_bf2(h, 0.f);
                float res = h - bflo(ph);
                uint32_t pl = pack_bf2(res, 0.f);
                shi[idx] = (uint16_t)ph;
                slo[idx] = (uint16_t)pl;
            } else {
                out[dir * HID + (size_t)t * outT + (size_t)b * outB + u] = h;
            }
        }
        __syncthreads();
        xg0 = xg0n;
        xg1 = xg1n;
    }
}

// ---------------- launch ------------------------------------------------------
extern "C" void kernel_launch(void* const* d_in, const int* in_sizes, int n_in,
                              void* d_out, int out_size)
{
    const float* x        = (const float*)d_in[0];
    // d_in[1] = lengths (unused, as in the reference)
    const float* Wih_fw1  = (const float*)d_in[2];
    const float* Whh_fw1  = (const float*)d_in[3];
    const float* bih_fw1  = (const float*)d_in[4];
    const float* bhh_fw1  = (const float*)d_in[5];
    const float* Wih_bw1  = (const float*)d_in[6];
    const float* Whh_bw1  = (const float*)d_in[7];
    const float* bih_bw1  = (const float*)d_in[8];
    const float* bhh_bw1  = (const float*)d_in[9];
    const float* Wih_fw2  = (const float*)d_in[10];
    const float* Whh_fw2  = (const float*)d_in[11];
    const float* bih_fw2  = (const float*)d_in[12];
    const float* bhh_fw2  = (const float*)d_in[13];
    const float* Wih_bw2  = (const float*)d_in[14];
    const float* Whh_bw2  = (const float*)d_in[15];
    const float* bih_bw2  = (const float*)d_in[16];
    const float* bhh_bw2  = (const float*)d_in[17];
    float* out = (float*)d_out;

    float *xg;
    uint16_t *ahi, *alo, *whi, *wlo;
    cudaGetSymbolAddress((void**)&xg,  g_xg);
    cudaGetSymbolAddress((void**)&ahi, g_ahi);
    cudaGetSymbolAddress((void**)&alo, g_alo);
    cudaGetSymbolAddress((void**)&whi, g_whi);
    cudaGetSymbolAddress((void**)&wlo, g_wlo);

    cudaFuncSetAttribute(lstm_rec2, cudaFuncAttributeMaxDynamicSharedMemorySize,
                         REC2_SMEM);
    cudaFuncSetAttribute(gemm_tc, cudaFuncAttributeMaxDynamicSharedMemorySize,
                         GEMM_SMEM);

    const int M = TSEQ * BATCH;          // 65536

    // 0) one-time weight splits (tiny)
    conv_split<<<(512 * 128 / 4 + 255) / 256, 256>>>(
        (const float4*)Wih_fw1, (uint2*)(whi + WOFF_FW1), (uint2*)(wlo + WOFF_FW1), 512 * 128 / 4);
    conv_split<<<(512 * 128 / 4 + 255) / 256, 256>>>(
        (const float4*)Wih_bw1, (uint2*)(whi + WOFF_BW1), (uint2*)(wlo + WOFF_BW1), 512 * 128 / 4);
    conv_split<<<(512 * 256 / 4 + 255) / 256, 256>>>(
        (const float4*)Wih_fw2, (uint2*)(whi + WOFF_FW2), (uint2*)(wlo + WOFF_FW2), 512 * 256 / 4);
    conv_split<<<(512 * 256 / 4 + 255) / 256, 256>>>(
        (const float4*)Wih_bw2, (uint2*)(whi + WOFF_BW2), (uint2*)(wlo + WOFF_BW2), 512 * 256 / 4);

    // 1) x: transpose + split -> Ahi/Alo [T*B, 128]
    conv_x<<<(TSEQ * BATCH * 32 + 255) / 256, 256>>>(
        (const float4*)x, (uint2*)ahi, (uint2*)alo);

    // 2) layer-1 input projections (tensor cores; bias folded in)
    dim3 gg(M / 128, G4 / 128);
    gemm_tc<<<gg, 256, GEMM_SMEM>>>(ahi, alo, whi + WOFF_FW1, wlo + WOFF_FW1,
                                    bih_fw1, bhh_fw1, xg,          128);
    gemm_tc<<<gg, 256, GEMM_SMEM>>>(ahi, alo, whi + WOFF_BW1, wlo + WOFF_BW1,
                                    bih_bw1, bhh_bw1, xg + XGHALF, 128);

    // 3) layer-1 recurrence -> bf16 hi/lo split directly into Ahi/Alo [T*B,256]
    lstm_rec2<<<dim3(BATCH, 2), 256, REC2_SMEM>>>(
        xg, Whh_fw1, Whh_bw1, nullptr, 0, 0, ahi, alo);

    // 4) layer-2 input projections (K = 256)
    gemm_tc<<<gg, 256, GEMM_SMEM>>>(ahi, alo, whi + WOFF_FW2, wlo + WOFF_FW2,
                                    bih_fw2, bhh_fw2, xg,          256);
    gemm_tc<<<gg, 256, GEMM_SMEM>>>(ahi, alo, whi + WOFF_BW2, wlo + WOFF_BW2,
                                    bih_bw2, bhh_bw2, xg + XGHALF, 256);

    // 5) layer-2 recurrence -> d_out [B,T,256] (fp32)
    lstm_rec2<<<dim3(BATCH, 2), 256, REC2_SMEM>>>(
        xg, Whh_fw2, Whh_bw2, out, 256, TSEQ * 256, nullptr, nullptr);
}

// round 15
// speedup vs baseline: 1.1628x; 1.1628x over previous
#include <cuda_runtime.h>
#include <cuda_bf16.h>
#include <cstdint>

// Problem constants
#define TSEQ 1024
#define BATCH 64
#define HID 128
#define G4 512            // 4*HID
#define XGHALF (TSEQ*BATCH*G4)   // per-direction xg elements

// ---------------- scratch (static device globals; no allocations) -------------
__device__ float g_xg[2 * TSEQ * BATCH * G4];     // [dir][T][B][512]
__device__ uint16_t g_ahi[TSEQ * BATCH * 256];    // A hi (bf16), layer 1 or 2
__device__ uint16_t g_alo[TSEQ * BATCH * 256];    // A lo (bf16)
__device__ uint16_t g_whi[512 * 768];             // W hi: fw1|bw1|fw2|bw2
__device__ uint16_t g_wlo[512 * 768];             // W lo

// W offsets (bf16 elements) — fw1:128 cols, bw1:128, fw2:256, bw2:256
#define WOFF_FW1 0
#define WOFF_BW1 (512 * 128)
#define WOFF_FW2 (512 * 256)
#define WOFF_BW2 (512 * 512)

// ---------------- MUFU activations (short chains; limits exact at +/-inf) -----
__device__ __forceinline__ float fsig_mufu(float x) {
    float e;
    asm("ex2.approx.f32 %0, %1;" : "=f"(e) : "f"(-1.4426950408889634f * x));
    float r;
    asm("rcp.approx.f32 %0, %1;" : "=f"(r) : "f"(1.0f + e));
    return r;
}
__device__ __forceinline__ float ftanh_mufu(float x) {
    float e;
    asm("ex2.approx.f32 %0, %1;" : "=f"(e) : "f"(-2.8853900817779268f * x));
    float r;
    asm("rcp.approx.f32 %0, %1;" : "=f"(r) : "f"(1.0f + e));
    return fmaf(2.0f, r, -1.0f);
}

// ---------------- bf16 pack/unpack --------------------------------------------
__device__ __forceinline__ uint32_t pack_bf2(float lo, float hi) {
    uint32_t r;   // PTX: cvt.rn.bf16x2.f32 d, a(high), b(low)
    asm("cvt.rn.bf16x2.f32 %0, %1, %2;" : "=r"(r) : "f"(hi), "f"(lo));
    return r;
}
__device__ __forceinline__ float bflo(uint32_t b) {
    return __int_as_float((int)(b << 16));
}
__device__ __forceinline__ float bfhi(uint32_t b) {
    return __int_as_float((int)(b & 0xFFFF0000u));
}
__device__ __forceinline__ void split4(float4 v, uint2& hi, uint2& lo) {
    uint32_t h0 = pack_bf2(v.x, v.y), h1 = pack_bf2(v.z, v.w);
    uint32_t l0 = pack_bf2(v.x - bflo(h0), v.y - bfhi(h0));
    uint32_t l1 = pack_bf2(v.z - bflo(h1), v.w - bfhi(h1));
    hi = make_uint2(h0, h1);
    lo = make_uint2(l0, l1);
}

// ---------------- warp-MMA primitives (baseline PTX, sm_80+) -------------------
__device__ __forceinline__ uint32_t smem_u32(const void* p) {
    uint32_t a;
    asm("{ .reg .u64 t; cvta.to.shared.u64 t, %1; cvt.u32.u64 %0, t; }"
        : "=r"(a) : "l"(p));
    return a;
}
__device__ __forceinline__ void ldmx4(uint32_t* r, uint32_t addr) {
    asm volatile("ldmatrix.sync.aligned.m8n8.x4.shared.b16 {%0,%1,%2,%3}, [%4];"
                 : "=r"(r[0]), "=r"(r[1]), "=r"(r[2]), "=r"(r[3]) : "r"(addr));
}
__device__ __forceinline__ void mma16816(float* c, const uint32_t* a,
                                         const uint32_t* b) {
    asm volatile(
        "mma.sync.aligned.m16n8k16.row.col.f32.bf16.bf16.f32 "
        "{%0,%1,%2,%3}, {%4,%5,%6,%7}, {%8,%9}, {%0,%1,%2,%3};"
        : "+f"(c[0]), "+f"(c[1]), "+f"(c[2]), "+f"(c[3])
        : "r"(a[0]), "r"(a[1]), "r"(a[2]), "r"(a[3]), "r"(b[0]), "r"(b[1]));
}
__device__ __forceinline__ void cp16(uint32_t dst, const void* src) {
    asm volatile("cp.async.ca.shared.global [%0], [%1], 16;"
                 :: "r"(dst), "l"(src));
}
#define CP_COMMIT() asm volatile("cp.async.commit_group;" ::: "memory")
#define CP_WAIT0()  asm volatile("cp.async.wait_group 0;" ::: "memory")
// SW128-style swizzle for 128B-row tiles (row stride 128B = 64 bf16)
__device__ __forceinline__ uint32_t swz(uint32_t off) {
    return off ^ ((off >> 3) & 0x70);
}

// ---------------- converters ---------------------------------------------------
// x [B,T,128] -> (transpose to [T,B,128]) hi/lo bf16
__global__ void conv_x(const float4* __restrict__ x,
                       uint2* __restrict__ hi, uint2* __restrict__ lo) {
    int i = blockIdx.x * blockDim.x + threadIdx.x;   // over T*B*32 float4s
    if (i >= TSEQ * BATCH * 32) return;
    int t  = i >> 11;
    int r  = i & 2047;
    int b  = r >> 5;
    int k4 = r & 31;
    float4 v = x[((size_t)b * TSEQ + t) * 32 + k4];
    split4(v, hi[i], lo[i]);
}
// generic fp32 -> bf16 hi/lo split (n4 float4s)
__global__ void conv_split(const float4* __restrict__ src,
                           uint2* __restrict__ hi, uint2* __restrict__ lo,
                           int n4) {
    int i = blockIdx.x * blockDim.x + threadIdx.x;
    if (i >= n4) return;
    split4(src[i], hi[i], lo[i]);
}

// ---------------- tensor-core GEMM (bf16 pre-split, cp.async pipeline) ---------
// C[M,512] = A[M,K]*W[512,K]^T + bias1 + bias2.  Per CTA: 128x128 C-tile,
// 8 warps in 2(m)x4(n), each 64x32 via m16n8k16. K staged 64/iter, double-buffered.
#define KSTAGE 64
#define TILE_BY (128 * KSTAGE * 2)     // 16384 B per bf16 tile
#define STAGE_BY (4 * TILE_BY)         // AH, AL, BH, BL = 64 KB
#define GEMM_SMEM (2 * STAGE_BY)       // double buffer = 128 KB

__global__ __launch_bounds__(256, 1) void gemm_tc(
    const uint16_t* __restrict__ Ahi, const uint16_t* __restrict__ Alo,
    const uint16_t* __restrict__ Whi, const uint16_t* __restrict__ Wlo,
    const float* __restrict__ bias1, const float* __restrict__ bias2,
    float* __restrict__ C, int K)
{
    extern __shared__ __align__(1024) char smem[];
    uint32_t sb = smem_u32(smem);

    int tid = threadIdx.x;
    int wid = tid >> 5;
    int l   = tid & 31;
    int wm  = wid >> 2;          // 0..1  (64-row slab)
    int wn  = wid & 3;           // 0..3  (32-col slab)
    int bm  = blockIdx.x * 128;
    int bn  = blockIdx.y * 128;

    float acc[4][4][4];
#pragma unroll
    for (int i = 0; i < 4; i++)
#pragma unroll
        for (int jj = 0; jj < 4; jj++)
#pragma unroll
            for (int e = 0; e < 4; e++) acc[i][jj][e] = 0.f;

    // loader: thread -> row tid>>1, four 16B chunks at col-chunks (tid&1)*4+q
    int lrow = tid >> 1;
    const uint16_t* Arow_h = Ahi + (size_t)(bm + lrow) * K;
    const uint16_t* Arow_l = Alo + (size_t)(bm + lrow) * K;
    const uint16_t* Wrow_h = Whi + (size_t)(bn + lrow) * K;
    const uint16_t* Wrow_l = Wlo + (size_t)(bn + lrow) * K;

    // ldmatrix lane address components (within a 128x64 tile)
    int a_row = (l & 7) + ((l >> 3) & 1) * 8;
    int a_cb  = ((l >> 4) & 1) * 8;
    int b_row = (l & 7) + ((l >> 4) & 1) * 8;
    int b_cb  = ((l >> 3) & 1) * 8;

    int nst = K / KSTAGE;

    // --- stage loader (cp.async, 16 chunks per thread) ---
#define LOAD_STAGE(st, buf)                                                   \
    do {                                                                      \
        uint32_t base_ = sb + (buf) * STAGE_BY;                               \
        int k0_ = (st) * KSTAGE;                                              \
        _Pragma("unroll")                                                     \
        for (int q_ = 0; q_ < 4; q_++) {                                      \
            int c8_ = (tid & 1) * 4 + q_;                                     \
            uint32_t d_ = swz((uint32_t)(lrow * 128 + c8_ * 16));             \
            int so_ = k0_ + c8_ * 8;                                          \
            cp16(base_ + 0 * TILE_BY + d_, Arow_h + so_);                     \
            cp16(base_ + 1 * TILE_BY + d_, Arow_l + so_);                     \
            cp16(base_ + 2 * TILE_BY + d_, Wrow_h + so_);                     \
            cp16(base_ + 3 * TILE_BY + d_, Wrow_l + so_);                     \
        }                                                                     \
        CP_COMMIT();                                                          \
    } while (0)

    LOAD_STAGE(0, 0);

    for (int st = 0; st < nst; st++) {
        int buf = st & 1;
        CP_WAIT0();
        __syncthreads();
        if (st + 1 < nst) LOAD_STAGE(st + 1, buf ^ 1);

        uint32_t sAH = sb + buf * STAGE_BY;
        uint32_t sAL = sAH + TILE_BY;
        uint32_t sBH = sAH + 2 * TILE_BY;
        uint32_t sBL = sAH + 3 * TILE_BY;

#pragma unroll
        for (int kk = 0; kk < KSTAGE / 16; kk++) {
            int C0 = kk * 16;
            uint32_t bh[8], bl[8];
#pragma unroll
            for (int half = 0; half < 2; half++) {
                uint32_t off = swz((uint32_t)(
                    (wn * 32 + half * 16 + b_row) * 128 + (C0 + b_cb) * 2));
                ldmx4(bh + half * 4, sBH + off);
                ldmx4(bl + half * 4, sBL + off);
            }
#pragma unroll
            for (int mt = 0; mt < 4; mt++) {
                uint32_t off = swz((uint32_t)(
                    (wm * 64 + mt * 16 + a_row) * 128 + (C0 + a_cb) * 2));
                uint32_t ah[4], al[4];
                ldmx4(ah, sAH + off);
                ldmx4(al, sAL + off);
#pragma unroll
                for (int nt = 0; nt < 4; nt++) {
                    mma16816(acc[mt][nt], ah, bh + nt * 2);
                    mma16816(acc[mt][nt], al, bh + nt * 2);
                    mma16816(acc[mt][nt], ah, bl + nt * 2);
                }
            }
        }
        __syncthreads();
    }

    // epilogue: bias + store
    int crow = l >> 2;
    int ccol = (l & 3) * 2;
#pragma unroll
    for (int nt = 0; nt < 4; nt++) {
        int gc = bn + wn * 32 + nt * 8 + ccol;
        float b0 = __ldg(&bias1[gc])     + __ldg(&bias2[gc]);
        float b1 = __ldg(&bias1[gc + 1]) + __ldg(&bias2[gc + 1]);
#pragma unroll
        for (int mt = 0; mt < 4; mt++) {
            int gr = bm + wm * 64 + mt * 16 + crow;
            float* p0 = C + (size_t)gr * G4 + gc;
            p0[0] = acc[mt][nt][0] + b0;
            p0[1] = acc[mt][nt][1] + b1;
            float* p1 = C + (size_t)(gr + 8) * G4 + gc;
            p1[0] = acc[mt][nt][2] + b0;
            p1[1] = acc[mt][nt][3] + b1;
        }
    }
}

// ---------------- recurrent LSTM scan: 256 thr, shuffle exchange, 1 barrier ----
// Warp w handles units [16w, 16w+16). Lane 2k owns (i,g) of unit u=16w+k,
// lane 2k+1 owns (f,o) of the same u. Gate exchange = __shfl_xor(.,1).
// h ping-pong buffer -> ONE __syncthreads per step. SMEM WEIGHTS ARE SLOT-
// INDEXED BY tid (not by row) so warp access stays conflict-free (R14 bug fix).
#define RK2 88
#define SKQ2 ((128 - RK2) / 4)          // 10 smem quads per row
#define REC2_SMEM (SKQ2 * G4 * 16 + 2 * HID * 4)

__global__ __launch_bounds__(256, 1) void lstm_rec2(
    const float* __restrict__ xg,        // [dir][T][B][512]
    const float* __restrict__ Whh0,      // fw weights [512][128]
    const float* __restrict__ Whh1,      // bw weights [512][128]
    float* __restrict__ out,             // fp32 h output (layer 2) or unused
    int outT, int outB,                  // strides (floats) for t and b
    uint16_t* __restrict__ shi,          // if non-null: write bf16 hi/lo split
    uint16_t* __restrict__ slo)          //   at [t][b][dir*128+u] (layer 1)
{
    extern __shared__ float sm[];
    float4* ws4 = (float4*)sm;                   // SKQ2*512 quads: [q][slot]
    float* hbuf = sm + SKQ2 * 4 * G4;            // 2 x 128 ping-pong (16B align)

    int tid = threadIdx.x;
    int b   = blockIdx.x;
    int dir = blockIdx.y;
    const float* Whh = dir ? Whh1 : Whh0;

    int u   = (tid >> 5) * 16 + ((tid & 31) >> 1);   // hidden unit
    int odd = tid & 1;
    int r0 = u + odd * 128;              // i (even) / f (odd)
    int r1 = u + 256 + odd * 128;        // g (even) / o (odd)

    const float4* W0 = (const float4*)(Whh + (size_t)r0 * 128);
    const float4* W1 = (const float4*)(Whh + (size_t)r1 * 128);
    float w0[RK2], w1[RK2];
#pragma unroll
    for (int q = 0; q < RK2 / 4; q++) {
        float4 v = W0[q];
        w0[4 * q + 0] = v.x; w0[4 * q + 1] = v.y;
        w0[4 * q + 2] = v.z; w0[4 * q + 3] = v.w;
        v = W1[q];
        w1[4 * q + 0] = v.x; w1[4 * q + 1] = v.y;
        w1[4 * q + 2] = v.z; w1[4 * q + 3] = v.w;
    }
    // SLOT-indexed smem weights: slotA = tid, slotB = tid + 256 (conflict-free)
#pragma unroll
    for (int q = RK2 / 4; q < 32; q++) {
        ws4[(q - RK2 / 4) * G4 + tid]       = W0[q];
        ws4[(q - RK2 / 4) * G4 + 256 + tid] = W1[q];
    }

    if (tid < 2 * HID) hbuf[tid] = 0.f;
    float c = 0.f;
    __syncthreads();

    size_t xgb0 = (size_t)dir * XGHALF + (size_t)b * G4 + r0;
    size_t xgb1 = (size_t)dir * XGHALF + (size_t)b * G4 + r1;
    int t0 = dir ? (TSEQ - 1) : 0;
    float xg0 = __ldg(xg + xgb0 + (size_t)t0 * (BATCH * G4));
    float xg1 = __ldg(xg + xgb1 + (size_t)t0 * (BATCH * G4));

    for (int s = 0; s < TSEQ; s++) {
        int t = dir ? (TSEQ - 1 - s) : s;
        int tn = dir ? max(t - 1, 0) : min(t + 1, TSEQ - 1);
        float xg0n = __ldg(xg + xgb0 + (size_t)tn * (BATCH * G4));
        float xg1n = __ldg(xg + xgb1 + (size_t)tn * (BATCH * G4));

        const float4* hs4 = (const float4*)(hbuf + (s & 1) * HID);
        float a0 = xg0, a1 = 0.f, a2 = 0.f, a3 = 0.f;
        float b0 = xg1, b1 = 0.f, b2 = 0.f, b3 = 0.f;
#pragma unroll
        for (int q = 0; q < RK2 / 4; q++) {      // register half, both rows
            float4 hv = hs4[q];
            a0 += w0[4 * q + 0] * hv.x;
            a1 += w0[4 * q + 1] * hv.y;
            a2 += w0[4 * q + 2] * hv.z;
            a3 += w0[4 * q + 3] * hv.w;
            b0 += w1[4 * q + 0] * hv.x;
            b1 += w1[4 * q + 1] * hv.y;
            b2 += w1[4 * q + 2] * hv.z;
            b3 += w1[4 * q + 3] * hv.w;
        }
#pragma unroll
        for (int q = 0; q < SKQ2; q++) {         // smem half (slot-indexed)
            float4 hv = hs4[RK2 / 4 + q];
            float4 uq = ws4[q * G4 + tid];
            float4 vq = ws4[q * G4 + 256 + tid];
            a0 += uq.x * hv.x; a1 += uq.y * hv.y;
            a2 += uq.z * hv.z; a3 += uq.w * hv.w;
            b0 += vq.x * hv.x; b1 += vq.y * hv.y;
            b2 += vq.z * hv.z; b3 += vq.w * hv.w;
        }
        float pre0 = (a0 + a1) + (a2 + a3);      // i (even) / f (odd)
        float pre1 = (b0 + b1) + (b2 + b3);      // g (even) / o (odd)

        float v0 = fsig_mufu(pre0);                           // i or f
        float v1 = odd ? fsig_mufu(pre1) : ftanh_mufu(pre1);  // o or g

        // partner exchange within the lane pair
        float pv0 = __shfl_xor_sync(0xFFFFFFFFu, v0, 1);   // f (for even)
        float pv1 = __shfl_xor_sync(0xFFFFFFFFu, v1, 1);   // o (for even)

        float h = 0.f;
        if (!odd) {
            c = fmaf(pv0, c, v0 * v1);           // c = f*c + i*g
            h = pv1 * ftanh_mufu(c);             // h = o*tanh(c)
            hbuf[((s & 1) ^ 1) * HID + u] = h;
        }
        __syncthreads();
        // stores off the critical path (after the barrier, h in register)
        if (!odd) {
            if (shi) {
                size_t idx = (size_t)t * (BATCH * 256) + b * 256 + dir * 128 + u;
                uint32_t ph = pack_bf2(h, 0.f);
                float res = h - bflo(ph);
                uint32_t pl = pack_bf2(res, 0.f);
                shi[idx] = (uint16_t)ph;
                slo[idx] = (uint16_t)pl;
            } else {
                out[dir * HID + (size_t)t * outT + (size_t)b * outB + u] = h;
            }
        }
        xg0 = xg0n;
        xg1 = xg1n;
    }
}

// ---------------- launch ------------------------------------------------------
extern "C" void kernel_launch(void* const* d_in, const int* in_sizes, int n_in,
                              void* d_out, int out_size)
{
    const float* x        = (const float*)d_in[0];
    // d_in[1] = lengths (unused, as in the reference)
    const float* Wih_fw1  = (const float*)d_in[2];
    const float* Whh_fw1  = (const float*)d_in[3];
    const float* bih_fw1  = (const float*)d_in[4];
    const float* bhh_fw1  = (const float*)d_in[5];
    const float* Wih_bw1  = (const float*)d_in[6];
    const float* Whh_bw1  = (const float*)d_in[7];
    const float* bih_bw1  = (const float*)d_in[8];
    const float* bhh_bw1  = (const float*)d_in[9];
    const float* Wih_fw2  = (const float*)d_in[10];
    const float* Whh_fw2  = (const float*)d_in[11];
    const float* bih_fw2  = (const float*)d_in[12];
    const float* bhh_fw2  = (const float*)d_in[13];
    const float* Wih_bw2  = (const float*)d_in[14];
    const float* Whh_bw2  = (const float*)d_in[15];
    const float* bih_bw2  = (const float*)d_in[16];
    const float* bhh_bw2  = (const float*)d_in[17];
    float* out = (float*)d_out;

    float *xg;
    uint16_t *ahi, *alo, *whi, *wlo;
    cudaGetSymbolAddress((void**)&xg,  g_xg);
    cudaGetSymbolAddress((void**)&ahi, g_ahi);
    cudaGetSymbolAddress((void**)&alo, g_alo);
    cudaGetSymbolAddress((void**)&whi, g_whi);
    cudaGetSymbolAddress((void**)&wlo, g_wlo);

    cudaFuncSetAttribute(lstm_rec2, cudaFuncAttributeMaxDynamicSharedMemorySize,
                         REC2_SMEM);
    cudaFuncSetAttribute(gemm_tc, cudaFuncAttributeMaxDynamicSharedMemorySize,
                         GEMM_SMEM);

    const int M = TSEQ * BATCH;          // 65536

    // 0) one-time weight splits (tiny)
    conv_split<<<(512 * 128 / 4 + 255) / 256, 256>>>(
        (const float4*)Wih_fw1, (uint2*)(whi + WOFF_FW1), (uint2*)(wlo + WOFF_FW1), 512 * 128 / 4);
    conv_split<<<(512 * 128 / 4 + 255) / 256, 256>>>(
        (const float4*)Wih_bw1, (uint2*)(whi + WOFF_BW1), (uint2*)(wlo + WOFF_BW1), 512 * 128 / 4);
    conv_split<<<(512 * 256 / 4 + 255) / 256, 256>>>(
        (const float4*)Wih_fw2, (uint2*)(whi + WOFF_FW2), (uint2*)(wlo + WOFF_FW2), 512 * 256 / 4);
    conv_split<<<(512 * 256 / 4 + 255) / 256, 256>>>(
        (const float4*)Wih_bw2, (uint2*)(whi + WOFF_BW2), (uint2*)(wlo + WOFF_BW2), 512 * 256 / 4);

    // 1) x: transpose + split -> Ahi/Alo [T*B, 128]
    conv_x<<<(TSEQ * BATCH * 32 + 255) / 256, 256>>>(
        (const float4*)x, (uint2*)ahi, (uint2*)alo);

    // 2) layer-1 input projections (tensor cores; bias folded in)
    dim3 gg(M / 128, G4 / 128);
    gemm_tc<<<gg, 256, GEMM_SMEM>>>(ahi, alo, whi + WOFF_FW1, wlo + WOFF_FW1,
                                    bih_fw1, bhh_fw1, xg,          128);
    gemm_tc<<<gg, 256, GEMM_SMEM>>>(ahi, alo, whi + WOFF_BW1, wlo + WOFF_BW1,
                                    bih_bw1, bhh_bw1, xg + XGHALF, 128);

    // 3) layer-1 recurrence -> bf16 hi/lo split directly into Ahi/Alo [T*B,256]
    lstm_rec2<<<dim3(BATCH, 2), 256, REC2_SMEM>>>(
        xg, Whh_fw1, Whh_bw1, nullptr, 0, 0, ahi, alo);

    // 4) layer-2 input projections (K = 256)
    gemm_tc<<<gg, 256, GEMM_SMEM>>>(ahi, alo, whi + WOFF_FW2, wlo + WOFF_FW2,
                                    bih_fw2, bhh_fw2, xg,          256);
    gemm_tc<<<gg, 256, GEMM_SMEM>>>(ahi, alo, whi + WOFF_BW2, wlo + WOFF_BW2,
                                    bih_bw2, bhh_bw2, xg + XGHALF, 256);

    // 5) layer-2 recurrence -> d_out [B,T,256] (fp32)
    lstm_rec2<<<dim3(BATCH, 2), 256, REC2_SMEM>>>(
        xg, Whh_fw2, Whh_bw2, out, 256, TSEQ * 256, nullptr, nullptr);
}

// round 16
// speedup vs baseline: 1.4943x; 1.2851x over previous
#include <cuda_runtime.h>
#include <cuda_bf16.h>
#include <cstdint>

// Problem constants
#define TSEQ 1024
#define BATCH 64
#define HID 128
#define G4 512            // 4*HID
#define XGHALF (TSEQ*BATCH*G4)   // per-direction xg elements

// ---------------- scratch (static device globals; no allocations) -------------
__device__ float g_xg[2 * TSEQ * BATCH * G4];     // [dir][T][B][512]
__device__ uint16_t g_ahi[TSEQ * BATCH * 256];    // A hi (bf16), layer 1 or 2
__device__ uint16_t g_alo[TSEQ * BATCH * 256];    // A lo (bf16)
__device__ uint16_t g_whi[512 * 768];             // W hi: fw1|bw1|fw2|bw2
__device__ uint16_t g_wlo[512 * 768];             // W lo

// W offsets (bf16 elements) — fw1:128 cols, bw1:128, fw2:256, bw2:256
#define WOFF_FW1 0
#define WOFF_BW1 (512 * 128)
#define WOFF_FW2 (512 * 256)
#define WOFF_BW2 (512 * 512)

// ---------------- MUFU activations (short chains; limits exact at +/-inf) -----
__device__ __forceinline__ float fsig_mufu(float x) {
    float e;
    asm("ex2.approx.f32 %0, %1;" : "=f"(e) : "f"(-1.4426950408889634f * x));
    float r;
    asm("rcp.approx.f32 %0, %1;" : "=f"(r) : "f"(1.0f + e));
    return r;
}
__device__ __forceinline__ float ftanh_mufu(float x) {
    float e;
    asm("ex2.approx.f32 %0, %1;" : "=f"(e) : "f"(-2.8853900817779268f * x));
    float r;
    asm("rcp.approx.f32 %0, %1;" : "=f"(r) : "f"(1.0f + e));
    return fmaf(2.0f, r, -1.0f);
}

// ---------------- bf16 pack/unpack --------------------------------------------
__device__ __forceinline__ uint32_t pack_bf2(float lo, float hi) {
    uint32_t r;   // PTX: cvt.rn.bf16x2.f32 d, a(high), b(low)
    asm("cvt.rn.bf16x2.f32 %0, %1, %2;" : "=r"(r) : "f"(hi), "f"(lo));
    return r;
}
__device__ __forceinline__ float bflo(uint32_t b) {
    return __int_as_float((int)(b << 16));
}
__device__ __forceinline__ float bfhi(uint32_t b) {
    return __int_as_float((int)(b & 0xFFFF0000u));
}
__device__ __forceinline__ void split4(float4 v, uint2& hi, uint2& lo) {
    uint32_t h0 = pack_bf2(v.x, v.y), h1 = pack_bf2(v.z, v.w);
    uint32_t l0 = pack_bf2(v.x - bflo(h0), v.y - bfhi(h0));
    uint32_t l1 = pack_bf2(v.z - bflo(h1), v.w - bfhi(h1));
    hi = make_uint2(h0, h1);
    lo = make_uint2(l0, l1);
}

// ---------------- warp-MMA primitives (baseline PTX, sm_80+) -------------------
__device__ __forceinline__ uint32_t smem_u32(const void* p) {
    uint32_t a;
    asm("{ .reg .u64 t; cvta.to.shared.u64 t, %1; cvt.u32.u64 %0, t; }"
        : "=r"(a) : "l"(p));
    return a;
}
__device__ __forceinline__ void ldmx4(uint32_t* r, uint32_t addr) {
    asm volatile("ldmatrix.sync.aligned.m8n8.x4.shared.b16 {%0,%1,%2,%3}, [%4];"
                 : "=r"(r[0]), "=r"(r[1]), "=r"(r[2]), "=r"(r[3]) : "r"(addr));
}
__device__ __forceinline__ void mma16816(float* c, const uint32_t* a,
                                         const uint32_t* b) {
    asm volatile(
        "mma.sync.aligned.m16n8k16.row.col.f32.bf16.bf16.f32 "
        "{%0,%1,%2,%3}, {%4,%5,%6,%7}, {%8,%9}, {%0,%1,%2,%3};"
        : "+f"(c[0]), "+f"(c[1]), "+f"(c[2]), "+f"(c[3])
        : "r"(a[0]), "r"(a[1]), "r"(a[2]), "r"(a[3]), "r"(b[0]), "r"(b[1]));
}
__device__ __forceinline__ void cp16(uint32_t dst, const void* src) {
    asm volatile("cp.async.ca.shared.global [%0], [%1], 16;"
                 :: "r"(dst), "l"(src));
}
#define CP_COMMIT() asm volatile("cp.async.commit_group;" ::: "memory")
#define CP_WAIT0()  asm volatile("cp.async.wait_group 0;" ::: "memory")
// SW128-style swizzle for 128B-row tiles (row stride 128B = 64 bf16)
__device__ __forceinline__ uint32_t swz(uint32_t off) {
    return off ^ ((off >> 3) & 0x70);
}

// ---------------- converters ---------------------------------------------------
// x [B,T,128] -> (transpose to [T,B,128]) hi/lo bf16
__global__ void conv_x(const float4* __restrict__ x,
                       uint2* __restrict__ hi, uint2* __restrict__ lo) {
    int i = blockIdx.x * blockDim.x + threadIdx.x;   // over T*B*32 float4s
    if (i >= TSEQ * BATCH * 32) return;
    int t  = i >> 11;
    int r  = i & 2047;
    int b  = r >> 5;
    int k4 = r & 31;
    float4 v = x[((size_t)b * TSEQ + t) * 32 + k4];
    split4(v, hi[i], lo[i]);
}
// generic fp32 -> bf16 hi/lo split (n4 float4s)
__global__ void conv_split(const float4* __restrict__ src,
                           uint2* __restrict__ hi, uint2* __restrict__ lo,
                           int n4) {
    int i = blockIdx.x * blockDim.x + threadIdx.x;
    if (i >= n4) return;
    split4(src[i], hi[i], lo[i]);
}
// all four Wih weights -> packed hi/lo arena in ONE kernel.
// uint2 units: fw1 [0,16384), bw1 [16384,32768), fw2 [32768,65536), bw2 [65536,98304)
__global__ void conv_w(const float4* __restrict__ w0, const float4* __restrict__ w1,
                       const float4* __restrict__ w2, const float4* __restrict__ w3,
                       uint2* __restrict__ hi, uint2* __restrict__ lo) {
    int i = blockIdx.x * blockDim.x + threadIdx.x;
    if (i >= 98304) return;
    float4 v;
    if      (i < 16384) v = w0[i];
    else if (i < 32768) v = w1[i - 16384];
    else if (i < 65536) v = w2[i - 32768];
    else                v = w3[i - 65536];
    split4(v, hi[i], lo[i]);
}

// ---------------- tensor-core GEMM (bf16 pre-split, cp.async pipeline) ---------
// C[M,512] = A[M,K]*W[512,K]^T + bias1 + bias2, both directions in one launch:
// blockIdx.z = dir; W base += dir*512*K; C += dir*XGHALF; per-dir bias pair.
// Per CTA: 128x128 C-tile, 8 warps 2(m)x4(n), m16n8k16, K staged 64, dbl-buffered.
#define KSTAGE 64
#define TILE_BY (128 * KSTAGE * 2)     // 16384 B per bf16 tile
#define STAGE_BY (4 * TILE_BY)         // AH, AL, BH, BL = 64 KB
#define GEMM_SMEM (2 * STAGE_BY)       // double buffer = 128 KB

__global__ __launch_bounds__(256, 1) void gemm_tc(
    const uint16_t* __restrict__ Ahi, const uint16_t* __restrict__ Alo,
    const uint16_t* __restrict__ Whi_base, const uint16_t* __restrict__ Wlo_base,
    const float* __restrict__ b1f, const float* __restrict__ b2f,
    const float* __restrict__ b1b, const float* __restrict__ b2b,
    float* __restrict__ Cbase, int K)
{
    extern __shared__ __align__(1024) char smem[];
    uint32_t sb = smem_u32(smem);

    int dir = blockIdx.z;
    const uint16_t* Whi = Whi_base + (size_t)dir * 512 * K;
    const uint16_t* Wlo = Wlo_base + (size_t)dir * 512 * K;
    const float* bias1 = dir ? b1b : b1f;
    const float* bias2 = dir ? b2b : b2f;
    float* C = Cbase + (size_t)dir * XGHALF;

    int tid = threadIdx.x;
    int wid = tid >> 5;
    int l   = tid & 31;
    int wm  = wid >> 2;          // 0..1  (64-row slab)
    int wn  = wid & 3;           // 0..3  (32-col slab)
    int bm  = blockIdx.x * 128;
    int bn  = blockIdx.y * 128;

    float acc[4][4][4];
#pragma unroll
    for (int i = 0; i < 4; i++)
#pragma unroll
        for (int jj = 0; jj < 4; jj++)
#pragma unroll
            for (int e = 0; e < 4; e++) acc[i][jj][e] = 0.f;

    int lrow = tid >> 1;
    const uint16_t* Arow_h = Ahi + (size_t)(bm + lrow) * K;
    const uint16_t* Arow_l = Alo + (size_t)(bm + lrow) * K;
    const uint16_t* Wrow_h = Whi + (size_t)(bn + lrow) * K;
    const uint16_t* Wrow_l = Wlo + (size_t)(bn + lrow) * K;

    int a_row = (l & 7) + ((l >> 3) & 1) * 8;
    int a_cb  = ((l >> 4) & 1) * 8;
    int b_row = (l & 7) + ((l >> 4) & 1) * 8;
    int b_cb  = ((l >> 3) & 1) * 8;

    int nst = K / KSTAGE;

#define LOAD_STAGE(st, buf)                                                   \
    do {                                                                      \
        uint32_t base_ = sb + (buf) * STAGE_BY;                               \
        int k0_ = (st) * KSTAGE;                                              \
        _Pragma("unroll")                                                     \
        for (int q_ = 0; q_ < 4; q_++) {                                      \
            int c8_ = (tid & 1) * 4 + q_;                                     \
            uint32_t d_ = swz((uint32_t)(lrow * 128 + c8_ * 16));             \
            int so_ = k0_ + c8_ * 8;                                          \
            cp16(base_ + 0 * TILE_BY + d_, Arow_h + so_);                     \
            cp16(base_ + 1 * TILE_BY + d_, Arow_l + so_);                     \
            cp16(base_ + 2 * TILE_BY + d_, Wrow_h + so_);                     \
            cp16(base_ + 3 * TILE_BY + d_, Wrow_l + so_);                     \
        }                                                                     \
        CP_COMMIT();                                                          \
    } while (0)

    LOAD_STAGE(0, 0);

    for (int st = 0; st < nst; st++) {
        int buf = st & 1;
        CP_WAIT0();
        __syncthreads();
        if (st + 1 < nst) LOAD_STAGE(st + 1, buf ^ 1);

        uint32_t sAH = sb + buf * STAGE_BY;
        uint32_t sAL = sAH + TILE_BY;
        uint32_t sBH = sAH + 2 * TILE_BY;
        uint32_t sBL = sAH + 3 * TILE_BY;

#pragma unroll
        for (int kk = 0; kk < KSTAGE / 16; kk++) {
            int C0 = kk * 16;
            uint32_t bh[8], bl[8];
#pragma unroll
            for (int half = 0; half < 2; half++) {
                uint32_t off = swz((uint32_t)(
                    (wn * 32 + half * 16 + b_row) * 128 + (C0 + b_cb) * 2));
                ldmx4(bh + half * 4, sBH + off);
                ldmx4(bl + half * 4, sBL + off);
            }
#pragma unroll
            for (int mt = 0; mt < 4; mt++) {
                uint32_t off = swz((uint32_t)(
                    (wm * 64 + mt * 16 + a_row) * 128 + (C0 + a_cb) * 2));
                uint32_t ah[4], al[4];
                ldmx4(ah, sAH + off);
                ldmx4(al, sAL + off);
#pragma unroll
                for (int nt = 0; nt < 4; nt++) {
                    mma16816(acc[mt][nt], ah, bh + nt * 2);
                    mma16816(acc[mt][nt], al, bh + nt * 2);
                    mma16816(acc[mt][nt], ah, bl + nt * 2);
                }
            }
        }
        __syncthreads();
    }

    int crow = l >> 2;
    int ccol = (l & 3) * 2;
#pragma unroll
    for (int nt = 0; nt < 4; nt++) {
        int gc = bn + wn * 32 + nt * 8 + ccol;
        float b0 = __ldg(&bias1[gc])     + __ldg(&bias2[gc]);
        float b1 = __ldg(&bias1[gc + 1]) + __ldg(&bias2[gc + 1]);
#pragma unroll
        for (int mt = 0; mt < 4; mt++) {
            int gr = bm + wm * 64 + mt * 16 + crow;
            float* p0 = C + (size_t)gr * G4 + gc;
            p0[0] = acc[mt][nt][0] + b0;
            p0[1] = acc[mt][nt][1] + b1;
            float* p1 = C + (size_t)(gr + 8) * G4 + gc;
            p1[0] = acc[mt][nt][2] + b0;
            p1[1] = acc[mt][nt][3] + b1;
        }
    }
}

// ---------------- recurrent LSTM scan (R12 proven form): 256 thr, 2 barriers ---
// Thread tid owns rows tid and tid+256:
//   tid<128:   row tid   = gate i (sigmoid),  row tid+256 = gate g (tanh)
//   tid>=128:  row tid   = gate f (sigmoid),  row tid+256 = gate o (sigmoid)
// h quads loaded once per thread feed both rows. Stores moved AFTER barrier 2
// (only change vs R12 — takes STG/pack off the phase-2 critical path).
#define RK2 88
#define SKQ2 ((128 - RK2) / 4)          // 10 smem quads per row
#define REC2_SMEM (SKQ2 * G4 * 16 + (HID + 2 * HID) * 4)

__global__ __launch_bounds__(256, 1) void lstm_rec2(
    const float* __restrict__ xg,        // [dir][T][B][512]
    const float* __restrict__ Whh0,      // fw weights [512][128]
    const float* __restrict__ Whh1,      // bw weights [512][128]
    float* __restrict__ out,             // fp32 h output (layer 2) or unused
    int outT, int outB,                  // strides (floats) for t and b
    uint16_t* __restrict__ shi,          // if non-null: write bf16 hi/lo split
    uint16_t* __restrict__ slo)          //   at [t][b][dir*128+j] (layer 1)
{
    extern __shared__ float sm[];
    float4* ws4 = (float4*)sm;                   // SKQ2*512 quads: [q][row]
    float* hs  = sm + SKQ2 * 4 * G4;             // 128 (16B aligned)
    float* gsF = hs + HID;                       // 128 (f gate)
    float* gsO = gsF + HID;                      // 128 (o gate)

    int tid = threadIdx.x;
    int b   = blockIdx.x;
    int dir = blockIdx.y;
    const float* Whh = dir ? Whh1 : Whh0;
    int r0 = tid, r1 = tid + 256;

    const float4* W0 = (const float4*)(Whh + (size_t)r0 * 128);
    const float4* W1 = (const float4*)(Whh + (size_t)r1 * 128);
    float w0[RK2], w1[RK2];
#pragma unroll
    for (int q = 0; q < RK2 / 4; q++) {
        float4 v = W0[q];
        w0[4 * q + 0] = v.x; w0[4 * q + 1] = v.y;
        w0[4 * q + 2] = v.z; w0[4 * q + 3] = v.w;
        v = W1[q];
        w1[4 * q + 0] = v.x; w1[4 * q + 1] = v.y;
        w1[4 * q + 2] = v.z; w1[4 * q + 3] = v.w;
    }
#pragma unroll
    for (int q = RK2 / 4; q < 32; q++) {
        ws4[(q - RK2 / 4) * G4 + r0] = W0[q];
        ws4[(q - RK2 / 4) * G4 + r1] = W1[q];
    }

    if (tid < HID) hs[tid] = 0.f;
    float c = 0.f;
    __syncthreads();

    size_t xgb0 = (size_t)dir * XGHALF + (size_t)b * G4 + r0;
    size_t xgb1 = xgb0 + 256;
    int t0 = dir ? (TSEQ - 1) : 0;
    float xg0 = __ldg(xg + xgb0 + (size_t)t0 * (BATCH * G4));
    float xg1 = __ldg(xg + xgb1 + (size_t)t0 * (BATCH * G4));
    bool lohalf = (tid < HID);

    for (int s = 0; s < TSEQ; s++) {
        int t = dir ? (TSEQ - 1 - s) : s;
        int tn = dir ? max(t - 1, 0) : min(t + 1, TSEQ - 1);
        float xg0n = __ldg(xg + xgb0 + (size_t)tn * (BATCH * G4));
        float xg1n = __ldg(xg + xgb1 + (size_t)tn * (BATCH * G4));

        const float4* hs4 = (const float4*)hs;
        float a0 = xg0, a1 = 0.f, a2 = 0.f, a3 = 0.f;
        float b0 = xg1, b1 = 0.f, b2 = 0.f, b3 = 0.f;
#pragma unroll
        for (int q = 0; q < RK2 / 4; q++) {      // register half, both rows
            float4 hv = hs4[q];
            a0 += w0[4 * q + 0] * hv.x;
            a1 += w0[4 * q + 1] * hv.y;
            a2 += w0[4 * q + 2] * hv.z;
            a3 += w0[4 * q + 3] * hv.w;
            b0 += w1[4 * q + 0] * hv.x;
            b1 += w1[4 * q + 1] * hv.y;
            b2 += w1[4 * q + 2] * hv.z;
            b3 += w1[4 * q + 3] * hv.w;
        }
#pragma unroll
        for (int q = 0; q < SKQ2; q++) {         // smem half, both rows
            float4 hv = hs4[RK2 / 4 + q];
            float4 u = ws4[q * G4 + r0];
            float4 v = ws4[q * G4 + r1];
            a0 += u.x * hv.x; a1 += u.y * hv.y;
            a2 += u.z * hv.z; a3 += u.w * hv.w;
            b0 += v.x * hv.x; b1 += v.y * hv.y;
            b2 += v.z * hv.z; b3 += v.w * hv.w;
        }
        float pre0 = (a0 + a1) + (a2 + a3);      // gate i (tid<128) / f
        float pre1 = (b0 + b1) + (b2 + b3);      // gate g (tid<128) / o

        float v0 = fsig_mufu(pre0);
        float v1, iv = 0.f, gv = 0.f;
        if (lohalf) {
            v1 = ftanh_mufu(pre1);               // g
            iv = v0; gv = v1;
        } else {
            v1 = fsig_mufu(pre1);                // o
            gsF[tid - HID] = v0;
            gsO[tid - HID] = v1;
        }
        __syncthreads();

        float h = 0.f;
        if (lohalf) {
            float fv = gsF[tid];
            float ov = gsO[tid];
            c = fmaf(fv, c, iv * gv);
            h = ov * ftanh_mufu(c);
            hs[tid] = h;
        }
        __syncthreads();
        // stores off the critical path (h still in register)
        if (lohalf) {
            if (shi) {
                size_t idx = (size_t)t * (BATCH * 256) + b * 256 + dir * 128 + tid;
                uint32_t ph = pack_bf2(h, 0.f);
                float res = h - bflo(ph);
                uint32_t pl = pack_bf2(res, 0.f);
                shi[idx] = (uint16_t)ph;
                slo[idx] = (uint16_t)pl;
            } else {
                out[dir * HID + (size_t)t * outT + (size_t)b * outB + tid] = h;
            }
        }
        xg0 = xg0n;
        xg1 = xg1n;
    }
}

// ---------------- launch ------------------------------------------------------
extern "C" void kernel_launch(void* const* d_in, const int* in_sizes, int n_in,
                              void* d_out, int out_size)
{
    const float* x        = (const float*)d_in[0];
    // d_in[1] = lengths (unused, as in the reference)
    const float* Wih_fw1  = (const float*)d_in[2];
    const float* Whh_fw1  = (const float*)d_in[3];
    const float* bih_fw1  = (const float*)d_in[4];
    const float* bhh_fw1  = (const float*)d_in[5];
    const float* Wih_bw1  = (const float*)d_in[6];
    const float* Whh_bw1  = (const float*)d_in[7];
    const float* bih_bw1  = (const float*)d_in[8];
    const float* bhh_bw1  = (const float*)d_in[9];
    const float* Wih_fw2  = (const float*)d_in[10];
    const float* Whh_fw2  = (const float*)d_in[11];
    const float* bih_fw2  = (const float*)d_in[12];
    const float* bhh_fw2  = (const float*)d_in[13];
    const float* Wih_bw2  = (const float*)d_in[14];
    const float* Whh_bw2  = (const float*)d_in[15];
    const float* bih_bw2  = (const float*)d_in[16];
    const float* bhh_bw2  = (const float*)d_in[17];
    float* out = (float*)d_out;

    float *xg;
    uint16_t *ahi, *alo, *whi, *wlo;
    cudaGetSymbolAddress((void**)&xg,  g_xg);
    cudaGetSymbolAddress((void**)&ahi, g_ahi);
    cudaGetSymbolAddress((void**)&alo, g_alo);
    cudaGetSymbolAddress((void**)&whi, g_whi);
    cudaGetSymbolAddress((void**)&wlo, g_wlo);

    cudaFuncSetAttribute(lstm_rec2, cudaFuncAttributeMaxDynamicSharedMemorySize,
                         REC2_SMEM);
    cudaFuncSetAttribute(gemm_tc, cudaFuncAttributeMaxDynamicSharedMemorySize,
                         GEMM_SMEM);

    const int M = TSEQ * BATCH;          // 65536

    // 0) one-time weight splits (single kernel for all four Wih)
    conv_w<<<(98304 + 255) / 256, 256>>>(
        (const float4*)Wih_fw1, (const float4*)Wih_bw1,
        (const float4*)Wih_fw2, (const float4*)Wih_bw2,
        (uint2*)whi, (uint2*)wlo);

    // 1) x: transpose + split -> Ahi/Alo [T*B, 128]
    conv_x<<<(TSEQ * BATCH * 32 + 255) / 256, 256>>>(
        (const float4*)x, (uint2*)ahi, (uint2*)alo);

    // 2) layer-1 input projections, both directions in one launch
    dim3 gg(M / 128, G4 / 128, 2);
    gemm_tc<<<gg, 256, GEMM_SMEM>>>(ahi, alo, whi + WOFF_FW1, wlo + WOFF_FW1,
                                    bih_fw1, bhh_fw1, bih_bw1, bhh_bw1, xg, 128);

    // 3) layer-1 recurrence -> bf16 hi/lo split directly into Ahi/Alo [T*B,256]
    lstm_rec2<<<dim3(BATCH, 2), 256, REC2_SMEM>>>(
        xg, Whh_fw1, Whh_bw1, nullptr, 0, 0, ahi, alo);

    // 4) layer-2 input projections (K = 256), both directions in one launch
    gemm_tc<<<gg, 256, GEMM_SMEM>>>(ahi, alo, whi + WOFF_FW2, wlo + WOFF_FW2,
                                    bih_fw2, bhh_fw2, bih_bw2, bhh_bw2, xg, 256);

    // 5) layer-2 recurrence -> d_out [B,T,256] (fp32)
    lstm_rec2<<<dim3(BATCH, 2), 256, REC2_SMEM>>>(
        xg, Whh_fw2, Whh_bw2, out, 256, TSEQ * 256, nullptr, nullptr);
}